// round 1
// baseline (speedup 1.0000x reference)
#include <cuda_runtime.h>
#include <math.h>

#define Hh 128
#define Ww 128
#define HW (Hh*Ww)
#define Cc 64
#define Oo 64
#define K2 9
#define CK 576            // C*K2
#define PIX 16            // pixels per block
#define SSTR 580          // padded smem row stride (floats), 16B-aligned, 580%32=4 -> <=2-way conflicts
#define NBLK (8*HW/PIX)   // 8192

// scratch: offsets (18 ch) + sigmoid(mask) (9 ch) per image: [B][27][H][W]
__device__ float g_offmask[8*27*HW];

// ---------------------------------------------------------------------------
// Kernel A: 3x3 conv producing 27 channels (18 offset + 9 mask w/ sigmoid)
// Block = 16 pixels in one row. smem im2col tile [16][576] (padded stride).
// ---------------------------------------------------------------------------
__global__ __launch_bounds__(256) void offmask_kernel(
    const float* __restrict__ x,
    const float* __restrict__ w_off, const float* __restrict__ b_off,
    const float* __restrict__ w_mask, const float* __restrict__ b_mask)
{
    __shared__ __align__(16) float s[PIX*SSTR];

    int blk = blockIdx.x;
    int b   = blk >> 10;            // 1024 tiles per image
    int rem = blk & 1023;
    int y   = rem >> 3;             // 8 tiles per row
    int x0  = (rem & 7) << 4;
    int tid = threadIdx.x;

    const float* xb = x + b*Cc*HW;

    // im2col fill (zero pad)
    for (int i = tid; i < CK*PIX; i += 256) {
        int p  = i & 15;
        int ck = i >> 4;
        int c  = ck / 9;
        int kk = ck - c*9;
        int yy = y - 1 + kk/3;
        int xx = x0 + p - 1 + (kk - (kk/3)*3);
        float v = 0.f;
        if (yy >= 0 && yy < Hh && xx >= 0 && xx < Ww)
            v = xb[c*HW + yy*Ww + xx];
        s[p*SSTR + ck] = v;
    }
    __syncthreads();

    int p  = tid & 15;
    int og = tid >> 4;              // 0..15
    int o0 = og;
    int o1 = og + 16;               // valid if < 27
    bool has1 = (o1 < 27);

    const float* wp0 = (o0 < 18) ? (w_off + o0*CK) : (w_mask + (o0-18)*CK);
    const float* wp1 = has1 ? ((o1 < 18) ? (w_off + o1*CK) : (w_mask + (o1-18)*CK)) : wp0;

    const float4* sp  = (const float4*)(s + p*SSTR);
    const float4* w40 = (const float4*)wp0;
    const float4* w41 = (const float4*)wp1;

    float acc0 = 0.f, acc1 = 0.f;
    #pragma unroll 4
    for (int q = 0; q < CK/4; q++) {
        float4 sv = sp[q];
        float4 a  = w40[q];
        acc0 += a.x*sv.x + a.y*sv.y + a.z*sv.z + a.w*sv.w;
        float4 c4 = w41[q];
        acc1 += c4.x*sv.x + c4.y*sv.y + c4.z*sv.z + c4.w*sv.w;
    }

    float bias0 = (o0 < 18) ? b_off[o0] : b_mask[o0-18];
    acc0 += bias0;
    if (o0 >= 18) acc0 = 1.f / (1.f + expf(-acc0));

    int gbase = b*27*HW + y*Ww + x0 + p;
    g_offmask[gbase + o0*HW] = acc0;

    if (has1) {
        float bias1 = (o1 < 18) ? b_off[o1] : b_mask[o1-18];
        acc1 += bias1;
        if (o1 >= 18) acc1 = 1.f / (1.f + expf(-acc1));
        g_offmask[gbase + o1*HW] = acc1;
    }
}

// ---------------------------------------------------------------------------
// Kernel B: deformable sampling + 64x576 GEMM per 16-pixel tile.
// Phase 1: threads 0..143 own one (p,k) pair: build 4 corner offsets + 4
//          mask-folded weights in registers, then gather-sample all 64
//          channels into smem tile s[p][c*9+k].
// Phase 2: 256 threads: p = tid%16, og = tid/16, each computes 4 outputs
//          o = og + 16j via float4 dot products (w_dcn L1-resident).
// ---------------------------------------------------------------------------
__global__ __launch_bounds__(256) void dcn_kernel(
    const float* __restrict__ x,
    const float* __restrict__ w_dcn, const float* __restrict__ b_dcn,
    float* __restrict__ out)
{
    __shared__ __align__(16) float s[PIX*SSTR];

    int blk = blockIdx.x;
    int b   = blk >> 10;
    int rem = blk & 1023;
    int y   = rem >> 3;
    int x0  = (rem & 7) << 4;
    int tid = threadIdx.x;

    const float* xb = x + b*Cc*HW;

    if (tid < 144) {
        int p = tid & 15;
        int k = tid >> 4;           // 0..8
        int xx = x0 + p;

        const float* gb = g_offmask + b*27*HW + y*Ww + xx;
        float dy = gb[(2*k    )*HW];
        float dx = gb[(2*k + 1)*HW];
        float m  = gb[(18 + k )*HW];

        int ki = k / 3;
        int kj = k - ki*3;
        float py = (float)(y  - 1 + ki) + dy;
        float px = (float)(xx - 1 + kj) + dx;

        float fy = floorf(py), fx = floorf(px);
        float wy1 = py - fy, wx1 = px - fx;
        float wy0 = 1.f - wy1, wx0 = 1.f - wx1;

        float vy0 = (fy      >= 0.f && fy      <= 127.f) ? 1.f : 0.f;
        float vy1 = (fy+1.f  >= 0.f && fy+1.f  <= 127.f) ? 1.f : 0.f;
        float vx0 = (fx      >= 0.f && fx      <= 127.f) ? 1.f : 0.f;
        float vx1 = (fx+1.f  >= 0.f && fx+1.f  <= 127.f) ? 1.f : 0.f;

        int y0 = (int)fminf(fmaxf(fy,      0.f), 127.f);
        int y1 = (int)fminf(fmaxf(fy+1.f,  0.f), 127.f);
        int xq0 = (int)fminf(fmaxf(fx,     0.f), 127.f);
        int xq1 = (int)fminf(fmaxf(fx+1.f, 0.f), 127.f);

        int o00 = y0*Ww + xq0, o01 = y0*Ww + xq1;
        int o10 = y1*Ww + xq0, o11 = y1*Ww + xq1;
        float w00 = wy0*wx0*vy0*vx0*m;
        float w01 = wy0*wx1*vy0*vx1*m;
        float w10 = wy1*wx0*vy1*vx0*m;
        float w11 = wy1*wx1*vy1*vx1*m;

        float* srow = s + p*SSTR + k;
        const float* xc = xb;
        #pragma unroll 4
        for (int c = 0; c < Cc; c++) {
            float v = w00*xc[o00] + w01*xc[o01] + w10*xc[o10] + w11*xc[o11];
            srow[c*9] = v;
            xc += HW;
        }
    }
    __syncthreads();

    int p  = tid & 15;
    int og = tid >> 4;              // 0..15; outputs og, og+16, og+32, og+48

    const float4* sp = (const float4*)(s + p*SSTR);
    const float4* w0 = (const float4*)(w_dcn + (og     )*CK);
    const float4* w1 = (const float4*)(w_dcn + (og + 16)*CK);
    const float4* w2 = (const float4*)(w_dcn + (og + 32)*CK);
    const float4* w3 = (const float4*)(w_dcn + (og + 48)*CK);

    float a0 = 0.f, a1 = 0.f, a2 = 0.f, a3 = 0.f;
    #pragma unroll 4
    for (int q = 0; q < CK/4; q++) {
        float4 sv = sp[q];
        float4 v0 = w0[q]; a0 += v0.x*sv.x + v0.y*sv.y + v0.z*sv.z + v0.w*sv.w;
        float4 v1 = w1[q]; a1 += v1.x*sv.x + v1.y*sv.y + v1.z*sv.z + v1.w*sv.w;
        float4 v2 = w2[q]; a2 += v2.x*sv.x + v2.y*sv.y + v2.z*sv.z + v2.w*sv.w;
        float4 v3 = w3[q]; a3 += v3.x*sv.x + v3.y*sv.y + v3.z*sv.z + v3.w*sv.w;
    }

    int obase = b*Oo*HW + y*Ww + x0 + p;
    out[obase + (og     )*HW] = a0 + b_dcn[og     ];
    out[obase + (og + 16)*HW] = a1 + b_dcn[og + 16];
    out[obase + (og + 32)*HW] = a2 + b_dcn[og + 32];
    out[obase + (og + 48)*HW] = a3 + b_dcn[og + 48];
}

extern "C" void kernel_launch(void* const* d_in, const int* in_sizes, int n_in,
                              void* d_out, int out_size)
{
    const float* x      = (const float*)d_in[0];
    const float* w_off  = (const float*)d_in[1];
    const float* b_off  = (const float*)d_in[2];
    const float* w_mask = (const float*)d_in[3];
    const float* b_mask = (const float*)d_in[4];
    const float* w_dcn  = (const float*)d_in[5];
    const float* b_dcn  = (const float*)d_in[6];
    float* out = (float*)d_out;

    offmask_kernel<<<NBLK, 256>>>(x, w_off, b_off, w_mask, b_mask);
    dcn_kernel<<<NBLK, 256>>>(x, w_dcn, b_dcn, out);
}

// round 2
// speedup vs baseline: 1.3159x; 1.3159x over previous
#include <cuda_runtime.h>
#include <math.h>

#define Hh 128
#define Ww 128
#define HW (Hh*Ww)
#define Cc 64
#define Oo 64
#define CK 576            // C*K2
#define PIX 16            // pixels per block
#define SSTR 580          // padded smem row stride (floats); 580 % 32 == 4 -> conflict-free LDS.128 in 8-lane phases
#define NBLK (8*HW/PIX)   // 8192
#define KC  144           // K-chunk (floats)
#define KC4 36            // K-chunk (float4)
#define NCHUNK (CK/KC)    // 4

#define SMEM_A ((PIX*SSTR + 27*KC)*4)   // 52672 B
#define SMEM_B ((PIX*SSTR + Oo*KC)*4)   // 73984 B

// scratch: offsets (18 ch) + sigmoid(mask) (9 ch) per image: [B][27][H][W]
__device__ float g_offmask[8*27*HW];

// ---------------------------------------------------------------------------
// Kernel A: 3x3 conv producing 27 channels (18 offset + 9 mask w/ sigmoid).
// im2col tile in smem + w staged through smem in K-chunks (broadcast LDS).
// ---------------------------------------------------------------------------
__global__ __launch_bounds__(256) void offmask_kernel(
    const float* __restrict__ x,
    const float* __restrict__ w_off, const float* __restrict__ b_off,
    const float* __restrict__ w_mask, const float* __restrict__ b_mask)
{
    extern __shared__ __align__(16) float smem[];
    float* s  = smem;                 // [PIX][SSTR] im2col
    float* sw = smem + PIX*SSTR;      // [27][KC] weight chunk
    float4* sw4 = (float4*)sw;

    int blk = blockIdx.x;
    int b   = blk >> 10;
    int rem = blk & 1023;
    int y   = rem >> 3;
    int x0  = (rem & 7) << 4;
    int tid = threadIdx.x;

    const float* xb = x + b*Cc*HW;

    // im2col fill (zero pad)
    for (int i = tid; i < CK*PIX; i += 256) {
        int p  = i & 15;
        int ck = i >> 4;
        int c  = ck / 9;
        int kk = ck - c*9;
        int yy = y - 1 + kk/3;
        int xx = x0 + p - 1 + (kk - (kk/3)*3);
        float v = 0.f;
        if (yy >= 0 && yy < Hh && xx >= 0 && xx < Ww)
            v = xb[c*HW + yy*Ww + xx];
        s[p*SSTR + ck] = v;
    }

    int p  = tid & 15;
    int og = tid >> 4;              // 0..15
    int o0 = og;
    int o1 = og + 16;
    bool has1 = (o1 < 27);
    int o1c = has1 ? o1 : 0;

    float acc0 = 0.f, acc1 = 0.f;

    for (int ch = 0; ch < NCHUNK; ch++) {
        __syncthreads();   // im2col ready (ch==0) / prev compute done reading sw
        // cooperative, coalesced load of w chunk: 27*KC4 = 972 float4
        for (int i = tid; i < 27*KC4; i += 256) {
            int o = i / KC4;
            int q = i - o*KC4;
            const float* src = (o < 18) ? (w_off + o*CK) : (w_mask + (o-18)*CK);
            sw4[i] = ((const float4*)src)[ch*KC4 + q];
        }
        __syncthreads();

        const float4* sp = (const float4*)(s + p*SSTR) + ch*KC4;
        const float4* wa = sw4 + o0*KC4;
        const float4* wb = sw4 + o1c*KC4;
        #pragma unroll 6
        for (int q = 0; q < KC4; q++) {
            float4 sv = sp[q];
            float4 a  = wa[q];
            acc0 += a.x*sv.x + a.y*sv.y + a.z*sv.z + a.w*sv.w;
            float4 c4 = wb[q];
            acc1 += c4.x*sv.x + c4.y*sv.y + c4.z*sv.z + c4.w*sv.w;
        }
    }

    float bias0 = (o0 < 18) ? b_off[o0] : b_mask[o0-18];
    acc0 += bias0;
    if (o0 >= 18) acc0 = 1.f / (1.f + expf(-acc0));

    int gbase = b*27*HW + y*Ww + x0 + p;
    g_offmask[gbase + o0*HW] = acc0;

    if (has1) {
        float bias1 = (o1 < 18) ? b_off[o1] : b_mask[o1-18];
        acc1 += bias1;
        if (o1 >= 18) acc1 = 1.f / (1.f + expf(-acc1));
        g_offmask[gbase + o1*HW] = acc1;
    }
}

// ---------------------------------------------------------------------------
// Kernel B: deformable sampling + 64x576 GEMM per 16-pixel tile.
// Phase 1: threads 0..143 gather-sample (mask folded into corner weights).
// Phase 2: w_dcn staged through smem in K-chunks; broadcast LDS for w,
//          conflict-free LDS.128 for the sample tile.
// ---------------------------------------------------------------------------
__global__ __launch_bounds__(256) void dcn_kernel(
    const float* __restrict__ x,
    const float* __restrict__ w_dcn, const float* __restrict__ b_dcn,
    float* __restrict__ out)
{
    extern __shared__ __align__(16) float smem[];
    float* s  = smem;                 // [PIX][SSTR] sampled tile
    float* sw = smem + PIX*SSTR;      // [64][KC] weight chunk
    float4* sw4 = (float4*)sw;

    int blk = blockIdx.x;
    int b   = blk >> 10;
    int rem = blk & 1023;
    int y   = rem >> 3;
    int x0  = (rem & 7) << 4;
    int tid = threadIdx.x;

    const float* xb = x + b*Cc*HW;

    if (tid < 144) {
        int p = tid & 15;
        int k = tid >> 4;           // 0..8
        int xx = x0 + p;

        const float* gb = g_offmask + b*27*HW + y*Ww + xx;
        float dy = gb[(2*k    )*HW];
        float dx = gb[(2*k + 1)*HW];
        float m  = gb[(18 + k )*HW];

        int ki = k / 3;
        int kj = k - ki*3;
        float py = (float)(y  - 1 + ki) + dy;
        float px = (float)(xx - 1 + kj) + dx;

        float fy = floorf(py), fx = floorf(px);
        float wy1 = py - fy, wx1 = px - fx;
        float wy0 = 1.f - wy1, wx0 = 1.f - wx1;

        float vy0 = (fy      >= 0.f && fy      <= 127.f) ? 1.f : 0.f;
        float vy1 = (fy+1.f  >= 0.f && fy+1.f  <= 127.f) ? 1.f : 0.f;
        float vx0 = (fx      >= 0.f && fx      <= 127.f) ? 1.f : 0.f;
        float vx1 = (fx+1.f  >= 0.f && fx+1.f  <= 127.f) ? 1.f : 0.f;

        int y0  = (int)fminf(fmaxf(fy,      0.f), 127.f);
        int y1  = (int)fminf(fmaxf(fy+1.f,  0.f), 127.f);
        int xq0 = (int)fminf(fmaxf(fx,      0.f), 127.f);
        int xq1 = (int)fminf(fmaxf(fx+1.f,  0.f), 127.f);

        int o00 = y0*Ww + xq0, o01 = y0*Ww + xq1;
        int o10 = y1*Ww + xq0, o11 = y1*Ww + xq1;
        float w00 = wy0*wx0*vy0*vx0*m;
        float w01 = wy0*wx1*vy0*vx1*m;
        float w10 = wy1*wx0*vy1*vx0*m;
        float w11 = wy1*wx1*vy1*vx1*m;

        float* srow = s + p*SSTR + k;
        const float* xc = xb;
        #pragma unroll 4
        for (int c = 0; c < Cc; c++) {
            float v = w00*xc[o00] + w01*xc[o01] + w10*xc[o10] + w11*xc[o11];
            srow[c*9] = v;
            xc += HW;
        }
    }

    int p  = tid & 15;
    int og = tid >> 4;              // outputs og, og+16, og+32, og+48

    float a0 = 0.f, a1 = 0.f, a2 = 0.f, a3 = 0.f;

    for (int ch = 0; ch < NCHUNK; ch++) {
        __syncthreads();   // sample tile ready (ch==0) / prev compute done
        // cooperative load of w chunk: 64*KC4 = 2304 float4 (9 per thread)
        #pragma unroll
        for (int j = 0; j < 9; j++) {
            int i = tid + j*256;
            int o = i / KC4;
            int q = i - o*KC4;
            sw4[i] = ((const float4*)(w_dcn + o*CK))[ch*KC4 + q];
        }
        __syncthreads();

        const float4* sp = (const float4*)(s + p*SSTR) + ch*KC4;
        const float4* w0 = sw4 + (og     )*KC4;
        const float4* w1 = sw4 + (og + 16)*KC4;
        const float4* w2 = sw4 + (og + 32)*KC4;
        const float4* w3 = sw4 + (og + 48)*KC4;

        #pragma unroll 4
        for (int q = 0; q < KC4; q++) {
            float4 sv = sp[q];
            float4 v0 = w0[q]; a0 += v0.x*sv.x + v0.y*sv.y + v0.z*sv.z + v0.w*sv.w;
            float4 v1 = w1[q]; a1 += v1.x*sv.x + v1.y*sv.y + v1.z*sv.z + v1.w*sv.w;
            float4 v2 = w2[q]; a2 += v2.x*sv.x + v2.y*sv.y + v2.z*sv.z + v2.w*sv.w;
            float4 v3 = w3[q]; a3 += v3.x*sv.x + v3.y*sv.y + v3.z*sv.z + v3.w*sv.w;
        }
    }

    int obase = b*Oo*HW + y*Ww + x0 + p;
    out[obase + (og     )*HW] = a0 + b_dcn[og     ];
    out[obase + (og + 16)*HW] = a1 + b_dcn[og + 16];
    out[obase + (og + 32)*HW] = a2 + b_dcn[og + 32];
    out[obase + (og + 48)*HW] = a3 + b_dcn[og + 48];
}

extern "C" void kernel_launch(void* const* d_in, const int* in_sizes, int n_in,
                              void* d_out, int out_size)
{
    const float* x      = (const float*)d_in[0];
    const float* w_off  = (const float*)d_in[1];
    const float* b_off  = (const float*)d_in[2];
    const float* w_mask = (const float*)d_in[3];
    const float* b_mask = (const float*)d_in[4];
    const float* w_dcn  = (const float*)d_in[5];
    const float* b_dcn  = (const float*)d_in[6];
    float* out = (float*)d_out;

    cudaFuncSetAttribute(offmask_kernel, cudaFuncAttributeMaxDynamicSharedMemorySize, SMEM_A);
    cudaFuncSetAttribute(dcn_kernel,     cudaFuncAttributeMaxDynamicSharedMemorySize, SMEM_B);

    offmask_kernel<<<NBLK, 256, SMEM_A>>>(x, w_off, b_off, w_mask, b_mask);
    dcn_kernel<<<NBLK, 256, SMEM_B>>>(x, w_dcn, b_dcn, out);
}

// round 3
// speedup vs baseline: 1.4071x; 1.0694x over previous
#include <cuda_runtime.h>
#include <math.h>

#define Hh 128
#define Ww 128
#define HW (Hh*Ww)
#define Cc 64
#define Oo 64
#define CK 576            // C*K2
#define PIX 32            // pixels per block
#define SSTR 580          // padded smem row stride (floats)
#define NBLK (8*HW/PIX)   // 4096
#define KC  96            // K-chunk (floats)
#define KC4 24            // K-chunk (float4)
#define NCHUNK (CK/KC)    // 6

#define SMEM_A ((PIX*SSTR + 27*KC)*4)   // 84608 B
#define SMEM_B ((PIX*SSTR + Oo*KC)*4)   // 98816 B

// scratch: offsets (18 ch) + sigmoid(mask) (9 ch) per image: [B][27][H][W]
__device__ float g_offmask[8*27*HW];

// ---------------------------------------------------------------------------
// Kernel A: 3x3 conv producing 27 channels (18 offset + 9 mask w/ sigmoid).
// im2col tile [32][580] + w chunk in smem; each thread: 2px x 2out tile.
// ---------------------------------------------------------------------------
__global__ __launch_bounds__(256) void offmask_kernel(
    const float* __restrict__ x,
    const float* __restrict__ w_off, const float* __restrict__ b_off,
    const float* __restrict__ w_mask, const float* __restrict__ b_mask)
{
    extern __shared__ __align__(16) float smem[];
    float* s  = smem;                 // [PIX][SSTR] im2col
    float4* sw4 = (float4*)(smem + PIX*SSTR);  // [27][KC4]

    int blk = blockIdx.x;
    int b   = blk >> 9;             // 512 tiles per image
    int rem = blk & 511;
    int y   = rem >> 2;             // 4 tiles per row
    int x0  = (rem & 3) << 5;
    int tid = threadIdx.x;

    const float* xb = x + b*Cc*HW;

    // im2col fill (zero pad): 576*32 elems
    for (int i = tid; i < CK*PIX; i += 256) {
        int p  = i & 31;
        int ck = i >> 5;
        int c  = ck / 9;
        int kk = ck - c*9;
        int yy = y - 1 + kk/3;
        int xx = x0 + p - 1 + (kk - (kk/3)*3);
        float v = 0.f;
        if (yy >= 0 && yy < Hh && xx >= 0 && xx < Ww)
            v = xb[c*HW + yy*Ww + xx];
        s[p*SSTR + ck] = v;
    }

    int tx = tid & 15;              // px pair {tx, tx+16}
    int og = tid >> 4;              // out pair {og, og+16}
    bool has1 = (og + 16 < 27);
    int o1c = has1 ? og + 16 : 0;

    float a00=0.f, a01=0.f, a10=0.f, a11=0.f;   // [px][out]

    for (int ch = 0; ch < NCHUNK; ch++) {
        __syncthreads();
        // cooperative load of w chunk: 27*24 = 648 float4
        for (int i = tid; i < 27*KC4; i += 256) {
            int o = i / KC4;
            int q = i - o*KC4;
            const float* src = (o < 18) ? (w_off + o*CK) : (w_mask + (o-18)*CK);
            sw4[i] = ((const float4*)src)[ch*KC4 + q];
        }
        __syncthreads();

        const float4* s0 = (const float4*)(s + tx*SSTR) + ch*KC4;
        const float4* s1 = (const float4*)(s + (tx+16)*SSTR) + ch*KC4;
        const float4* w0 = sw4 + og*KC4;
        const float4* w1 = sw4 + o1c*KC4;
        #pragma unroll 6
        for (int q = 0; q < KC4; q++) {
            float4 u = s0[q];
            float4 v = s1[q];
            float4 wa = w0[q];
            float4 wb = w1[q];
            a00 += wa.x*u.x + wa.y*u.y + wa.z*u.z + wa.w*u.w;
            a10 += wa.x*v.x + wa.y*v.y + wa.z*v.z + wa.w*v.w;
            a01 += wb.x*u.x + wb.y*u.y + wb.z*u.z + wb.w*u.w;
            a11 += wb.x*v.x + wb.y*v.y + wb.z*v.z + wb.w*v.w;
        }
    }

    int gbase = b*27*HW + y*Ww + x0;
    {
        float bias = (og < 18) ? b_off[og] : b_mask[og-18];
        float r0 = a00 + bias, r1 = a10 + bias;
        if (og >= 18) { r0 = 1.f/(1.f+expf(-r0)); r1 = 1.f/(1.f+expf(-r1)); }
        g_offmask[gbase + og*HW + tx]      = r0;
        g_offmask[gbase + og*HW + tx + 16] = r1;
    }
    if (has1) {
        int o1 = og + 16;
        float bias = (o1 < 18) ? b_off[o1] : b_mask[o1-18];
        float r0 = a01 + bias, r1 = a11 + bias;
        if (o1 >= 18) { r0 = 1.f/(1.f+expf(-r0)); r1 = 1.f/(1.f+expf(-r1)); }
        g_offmask[gbase + o1*HW + tx]      = r0;
        g_offmask[gbase + o1*HW + tx + 16] = r1;
    }
}

// ---------------------------------------------------------------------------
// Kernel B: deformable sampling + GEMM; each thread: 2px x 4out register tile.
// ---------------------------------------------------------------------------
__global__ __launch_bounds__(256) void dcn_kernel(
    const float* __restrict__ x,
    const float* __restrict__ w_dcn, const float* __restrict__ b_dcn,
    float* __restrict__ out)
{
    extern __shared__ __align__(16) float smem[];
    float* s  = smem;                 // [PIX][SSTR] sampled tile
    float4* sw4 = (float4*)(smem + PIX*SSTR);  // [64][KC4]

    int blk = blockIdx.x;
    int b   = blk >> 9;
    int rem = blk & 511;
    int y   = rem >> 2;
    int x0  = (rem & 3) << 5;
    int tid = threadIdx.x;

    const float* xb = x + b*Cc*HW;

    // sampling: 288 (p,k) tasks over 256 threads
    for (int task = tid; task < PIX*9; task += 256) {
        int p = task & 31;
        int k = task >> 5;          // 0..8
        int xx = x0 + p;

        const float* gb = g_offmask + b*27*HW + y*Ww + xx;
        float dy = gb[(2*k    )*HW];
        float dx = gb[(2*k + 1)*HW];
        float m  = gb[(18 + k )*HW];

        int ki = k / 3;
        int kj = k - ki*3;
        float py = (float)(y  - 1 + ki) + dy;
        float px = (float)(xx - 1 + kj) + dx;

        float fy = floorf(py), fx = floorf(px);
        float wy1 = py - fy, wx1 = px - fx;
        float wy0 = 1.f - wy1, wx0 = 1.f - wx1;

        float vy0 = (fy      >= 0.f && fy      <= 127.f) ? 1.f : 0.f;
        float vy1 = (fy+1.f  >= 0.f && fy+1.f  <= 127.f) ? 1.f : 0.f;
        float vx0 = (fx      >= 0.f && fx      <= 127.f) ? 1.f : 0.f;
        float vx1 = (fx+1.f  >= 0.f && fx+1.f  <= 127.f) ? 1.f : 0.f;

        int y0  = (int)fminf(fmaxf(fy,      0.f), 127.f);
        int y1  = (int)fminf(fmaxf(fy+1.f,  0.f), 127.f);
        int xq0 = (int)fminf(fmaxf(fx,      0.f), 127.f);
        int xq1 = (int)fminf(fmaxf(fx+1.f,  0.f), 127.f);

        int o00 = y0*Ww + xq0, o01 = y0*Ww + xq1;
        int o10 = y1*Ww + xq0, o11 = y1*Ww + xq1;
        float w00 = wy0*wx0*vy0*vx0*m;
        float w01 = wy0*wx1*vy0*vx1*m;
        float w10 = wy1*wx0*vy1*vx0*m;
        float w11 = wy1*wx1*vy1*vx1*m;

        float* srow = s + p*SSTR + k;
        const float* xc = xb;
        #pragma unroll 4
        for (int c = 0; c < Cc; c++) {
            float v = w00*xc[o00] + w01*xc[o01] + w10*xc[o10] + w11*xc[o11];
            srow[c*9] = v;
            xc += HW;
        }
    }

    int tx = tid & 15;              // px pair {tx, tx+16}
    int og = tid >> 4;              // outs og*4 .. og*4+3

    float acc[2][4];
    #pragma unroll
    for (int i = 0; i < 2; i++)
        #pragma unroll
        for (int j = 0; j < 4; j++) acc[i][j] = 0.f;

    for (int ch = 0; ch < NCHUNK; ch++) {
        __syncthreads();
        // cooperative load of w chunk: 64*24 = 1536 float4 (6 per thread)
        #pragma unroll
        for (int j = 0; j < 6; j++) {
            int i = tid + j*256;
            int o = i / KC4;
            int q = i - o*KC4;
            sw4[i] = ((const float4*)(w_dcn + o*CK))[ch*KC4 + q];
        }
        __syncthreads();

        const float4* s0 = (const float4*)(s + tx*SSTR) + ch*KC4;
        const float4* s1 = (const float4*)(s + (tx+16)*SSTR) + ch*KC4;
        const float4* w0 = sw4 + (og*4    )*KC4;
        const float4* w1 = sw4 + (og*4 + 1)*KC4;
        const float4* w2 = sw4 + (og*4 + 2)*KC4;
        const float4* w3 = sw4 + (og*4 + 3)*KC4;

        #pragma unroll 4
        for (int q = 0; q < KC4; q++) {
            float4 u = s0[q];
            float4 v = s1[q];
            float4 p0 = w0[q];
            acc[0][0] += p0.x*u.x + p0.y*u.y + p0.z*u.z + p0.w*u.w;
            acc[1][0] += p0.x*v.x + p0.y*v.y + p0.z*v.z + p0.w*v.w;
            float4 p1 = w1[q];
            acc[0][1] += p1.x*u.x + p1.y*u.y + p1.z*u.z + p1.w*u.w;
            acc[1][1] += p1.x*v.x + p1.y*v.y + p1.z*v.z + p1.w*v.w;
            float4 p2 = w2[q];
            acc[0][2] += p2.x*u.x + p2.y*u.y + p2.z*u.z + p2.w*u.w;
            acc[1][2] += p2.x*v.x + p2.y*v.y + p2.z*v.z + p2.w*v.w;
            float4 p3 = w3[q];
            acc[0][3] += p3.x*u.x + p3.y*u.y + p3.z*u.z + p3.w*u.w;
            acc[1][3] += p3.x*v.x + p3.y*v.y + p3.z*v.z + p3.w*v.w;
        }
    }

    int obase = b*Oo*HW + y*Ww + x0;
    #pragma unroll
    for (int j = 0; j < 4; j++) {
        int o = og*4 + j;
        float bias = b_dcn[o];
        out[obase + o*HW + tx]      = acc[0][j] + bias;
        out[obase + o*HW + tx + 16] = acc[1][j] + bias;
    }
}

extern "C" void kernel_launch(void* const* d_in, const int* in_sizes, int n_in,
                              void* d_out, int out_size)
{
    const float* x      = (const float*)d_in[0];
    const float* w_off  = (const float*)d_in[1];
    const float* b_off  = (const float*)d_in[2];
    const float* w_mask = (const float*)d_in[3];
    const float* b_mask = (const float*)d_in[4];
    const float* w_dcn  = (const float*)d_in[5];
    const float* b_dcn  = (const float*)d_in[6];
    float* out = (float*)d_out;

    cudaFuncSetAttribute(offmask_kernel, cudaFuncAttributeMaxDynamicSharedMemorySize, SMEM_A);
    cudaFuncSetAttribute(dcn_kernel,     cudaFuncAttributeMaxDynamicSharedMemorySize, SMEM_B);

    offmask_kernel<<<NBLK, 256, SMEM_A>>>(x, w_off, b_off, w_mask, b_mask);
    dcn_kernel<<<NBLK, 256, SMEM_B>>>(x, w_dcn, b_dcn, out);
}

// round 9
// speedup vs baseline: 2.0810x; 1.4789x over previous
#include <cuda_runtime.h>
#include <cuda_bf16.h>
#include <cstdint>
#include <math.h>

#define Hh 128
#define Ww 128
#define HW (Hh*Ww)
#define Cc 64
#define Oo 64
#define CK 576
#define PIX 32
#define SSTR 580
#define NBLK (8*HW/PIX)   // 4096
#define KC  96
#define KC4 24
#define NCHUNK (CK/KC)

#define SMEM_A ((PIX*SSTR + 27*KC)*4)

// A planes (bf16): [32 px][584] per plane, hi then lo
#define ASTRIDE 584                      // elements; 1168 B row stride
#define APLANE  (PIX*ASTRIDE*2)          // 37376 B per plane
#define SMEM_B  (2*APLANE)               // 74752 B

extern __shared__ __align__(16) char _smem_raw[];

// scratch
__device__ float g_offmask[8*27*HW];                 // [B][27][H][W]
// W fragments: [tile(8)][kk(36)][plane(2)][lane(32)] x uint2 (b0,b1)
__device__ __align__(16) uint2 g_wfrag[8*36*2*32];

// ---------------------------------------------------------------------------
// prep: pack w_dcn into mma.sync B-fragment order, bf16 hi/lo planes.
// K ordered as k = tap*64 + c  (tap-major, channel inner).
// ---------------------------------------------------------------------------
__device__ __forceinline__ float wdcn_at(const float* w_dcn, int o, int k) {
    int c = k & 63, tap = k >> 6;
    return w_dcn[o*CK + c*9 + tap];
}

__global__ void prep_w(const float* __restrict__ w_dcn) {
    int i = blockIdx.x*256 + threadIdx.x;    // 8*36*2*32 = 18432
    if (i >= 8*36*2*32) return;
    int lane  = i & 31;
    int plane = (i >> 5) & 1;
    int kt    = i >> 6;                      // 0..287
    int kk    = kt % 36;
    int tile  = kt / 36;
    int g  = lane >> 2;
    int t4 = lane & 3;
    int o  = tile*8 + g;
    int k0 = kk*16 + t4*2;

    float w0 = wdcn_at(w_dcn, o, k0);
    float w1 = wdcn_at(w_dcn, o, k0+1);
    float w2 = wdcn_at(w_dcn, o, k0+8);
    float w3 = wdcn_at(w_dcn, o, k0+9);

    __nv_bfloat16 v0, v1, v2, v3;
    if (plane == 0) {
        v0 = __float2bfloat16(w0); v1 = __float2bfloat16(w1);
        v2 = __float2bfloat16(w2); v3 = __float2bfloat16(w3);
    } else {
        v0 = __float2bfloat16(w0 - __bfloat162float(__float2bfloat16(w0)));
        v1 = __float2bfloat16(w1 - __bfloat162float(__float2bfloat16(w1)));
        v2 = __float2bfloat16(w2 - __bfloat162float(__float2bfloat16(w2)));
        v3 = __float2bfloat16(w3 - __bfloat162float(__float2bfloat16(w3)));
    }
    __nv_bfloat162 p0; p0.x = v0; p0.y = v1;
    __nv_bfloat162 p1; p1.x = v2; p1.y = v3;
    uint2 r;
    r.x = *(uint32_t*)&p0;
    r.y = *(uint32_t*)&p1;
    g_wfrag[i] = r;
}

// ---------------------------------------------------------------------------
// Kernel A (unchanged): offset/mask conv
// ---------------------------------------------------------------------------
__global__ __launch_bounds__(256) void offmask_kernel(
    const float* __restrict__ x,
    const float* __restrict__ w_off, const float* __restrict__ b_off,
    const float* __restrict__ w_mask, const float* __restrict__ b_mask)
{
    float* smem = (float*)_smem_raw;
    float* s  = smem;
    float4* sw4 = (float4*)(smem + PIX*SSTR);

    int blk = blockIdx.x;
    int b   = blk >> 9;
    int rem = blk & 511;
    int y   = rem >> 2;
    int x0  = (rem & 3) << 5;
    int tid = threadIdx.x;

    const float* xb = x + b*Cc*HW;

    for (int i = tid; i < CK*PIX; i += 256) {
        int p  = i & 31;
        int ck = i >> 5;
        int c  = ck / 9;
        int kk = ck - c*9;
        int yy = y - 1 + kk/3;
        int xx = x0 + p - 1 + (kk - (kk/3)*3);
        float v = 0.f;
        if (yy >= 0 && yy < Hh && xx >= 0 && xx < Ww)
            v = xb[c*HW + yy*Ww + xx];
        s[p*SSTR + ck] = v;
    }

    int tx = tid & 15;
    int og = tid >> 4;
    bool has1 = (og + 16 < 27);
    int o1c = has1 ? og + 16 : 0;

    float a00=0.f, a01=0.f, a10=0.f, a11=0.f;

    for (int ch = 0; ch < NCHUNK; ch++) {
        __syncthreads();
        for (int i = tid; i < 27*KC4; i += 256) {
            int o = i / KC4;
            int q = i - o*KC4;
            const float* src = (o < 18) ? (w_off + o*CK) : (w_mask + (o-18)*CK);
            sw4[i] = ((const float4*)src)[ch*KC4 + q];
        }
        __syncthreads();

        const float4* s0 = (const float4*)(s + tx*SSTR) + ch*KC4;
        const float4* s1 = (const float4*)(s + (tx+16)*SSTR) + ch*KC4;
        const float4* w0 = sw4 + og*KC4;
        const float4* w1 = sw4 + o1c*KC4;
        #pragma unroll 6
        for (int q = 0; q < KC4; q++) {
            float4 u = s0[q];
            float4 v = s1[q];
            float4 wa = w0[q];
            float4 wb = w1[q];
            a00 += wa.x*u.x + wa.y*u.y + wa.z*u.z + wa.w*u.w;
            a10 += wa.x*v.x + wa.y*v.y + wa.z*v.z + wa.w*v.w;
            a01 += wb.x*u.x + wb.y*u.y + wb.z*u.z + wb.w*u.w;
            a11 += wb.x*v.x + wb.y*v.y + wb.z*v.z + wb.w*v.w;
        }
    }

    int gbase = b*27*HW + y*Ww + x0;
    {
        float bias = (og < 18) ? b_off[og] : b_mask[og-18];
        float r0 = a00 + bias, r1 = a10 + bias;
        if (og >= 18) { r0 = 1.f/(1.f+expf(-r0)); r1 = 1.f/(1.f+expf(-r1)); }
        g_offmask[gbase + og*HW + tx]      = r0;
        g_offmask[gbase + og*HW + tx + 16] = r1;
    }
    if (has1) {
        int o1 = og + 16;
        float bias = (o1 < 18) ? b_off[o1] : b_mask[o1-18];
        float r0 = a01 + bias, r1 = a11 + bias;
        if (o1 >= 18) { r0 = 1.f/(1.f+expf(-r0)); r1 = 1.f/(1.f+expf(-r1)); }
        g_offmask[gbase + o1*HW + tx]      = r0;
        g_offmask[gbase + o1*HW + tx + 16] = r1;
    }
}

// ---------------------------------------------------------------------------
// Kernel B: sampling -> bf16 hi/lo smem planes -> mma.sync bf16 GEMM.
// Block = 32 pixels x 64 outputs, K = 576 (tap-major). 8 warps: warp w owns
// m-tile (w&1)*16 pixels x n16 outputs (w>>1)*16, 3 split passes per k16.
// ---------------------------------------------------------------------------
__global__ __launch_bounds__(256) void dcn_kernel(
    const float* __restrict__ x,
    const float* __restrict__ b_dcn,
    float* __restrict__ out)
{
    char* smA_h = _smem_raw;            // [32][584] bf16 (1168 B rows)
    char* smA_l = _smem_raw + APLANE;

    int blk = blockIdx.x;
    int b   = blk >> 9;
    int rem = blk & 511;
    int y   = rem >> 2;
    int x0  = (rem & 3) << 5;
    int tid = threadIdx.x;

    const float* xb = x + b*Cc*HW;

    // ---- sampling: 288 (p,tap) tasks ----
    for (int task = tid; task < PIX*9; task += 256) {
        int p = task & 31;
        int k = task >> 5;          // tap 0..8
        int xx = x0 + p;

        const float* gb = g_offmask + b*27*HW + y*Ww + xx;
        float dy = gb[(2*k    )*HW];
        float dx = gb[(2*k + 1)*HW];
        float m  = gb[(18 + k )*HW];

        int ki = k / 3;
        int kj = k - ki*3;
        float py = (float)(y  - 1 + ki) + dy;
        float px = (float)(xx - 1 + kj) + dx;

        float fy = floorf(py), fx = floorf(px);
        float wy1 = py - fy, wx1 = px - fx;
        float wy0 = 1.f - wy1, wx0 = 1.f - wx1;

        float vy0 = (fy      >= 0.f && fy      <= 127.f) ? 1.f : 0.f;
        float vy1 = (fy+1.f  >= 0.f && fy+1.f  <= 127.f) ? 1.f : 0.f;
        float vx0 = (fx      >= 0.f && fx      <= 127.f) ? 1.f : 0.f;
        float vx1 = (fx+1.f  >= 0.f && fx+1.f  <= 127.f) ? 1.f : 0.f;

        int y0  = (int)fminf(fmaxf(fy,      0.f), 127.f);
        int y1  = (int)fminf(fmaxf(fy+1.f,  0.f), 127.f);
        int xq0 = (int)fminf(fmaxf(fx,      0.f), 127.f);
        int xq1 = (int)fminf(fmaxf(fx+1.f,  0.f), 127.f);

        int o00 = y0*Ww + xq0, o01 = y0*Ww + xq1;
        int o10 = y1*Ww + xq0, o11 = y1*Ww + xq1;
        float w00 = wy0*wx0*vy0*vx0*m;
        float w01 = wy0*wx1*vy0*vx1*m;
        float w10 = wy1*wx0*vy1*vx0*m;
        float w11 = wy1*wx1*vy1*vx1*m;

        // row p, k-range tap*64 .. +63; store bf16x2 pairs
        uint32_t rowoff = (uint32_t)p*1168u + (uint32_t)k*128u;
        const float* xc = xb;
        #pragma unroll 8
        for (int c = 0; c < Cc; c += 2) {
            const float* c0 = xc;
            const float* c1 = xc + HW;
            float v0 = w00*c0[o00] + w01*c0[o01] + w10*c0[o10] + w11*c0[o11];
            float v1 = w00*c1[o00] + w01*c1[o01] + w10*c1[o10] + w11*c1[o11];
            __nv_bfloat16 h0 = __float2bfloat16(v0);
            __nv_bfloat16 h1 = __float2bfloat16(v1);
            __nv_bfloat16 l0 = __float2bfloat16(v0 - __bfloat162float(h0));
            __nv_bfloat16 l1 = __float2bfloat16(v1 - __bfloat162float(h1));
            __nv_bfloat162 hh; hh.x = h0; hh.y = h1;
            __nv_bfloat162 ll; ll.x = l0; ll.y = l1;
            *(uint32_t*)(smA_h + rowoff + c*2) = *(uint32_t*)&hh;
            *(uint32_t*)(smA_l + rowoff + c*2) = *(uint32_t*)&ll;
            xc += 2*HW;
        }
    }
    __syncthreads();

    // ---- GEMM: mma.sync bf16, hi/lo split ----
    int wid  = tid >> 5;
    int lane = tid & 31;
    int mrow = (wid & 1) * 16;          // pixel base within tile
    int ng   = wid >> 1;                // n16 group: outs ng*16 .. +15
    int g  = lane >> 2;
    int t4 = lane & 3;

    float d0[4] = {0.f,0.f,0.f,0.f};    // n8 tile 0
    float d1[4] = {0.f,0.f,0.f,0.f};    // n8 tile 1

    const uint2* fr0 = g_wfrag + ((ng*2    )*36)*2*32 + lane;  // tile 2*ng
    const uint2* fr1 = g_wfrag + ((ng*2 + 1)*36)*2*32 + lane;  // tile 2*ng+1

    uint32_t arow0 = (uint32_t)(mrow + g)*1168u + (uint32_t)t4*4u;
    uint32_t arow1 = arow0 + 8u*1168u;

    #pragma unroll 4
    for (int kk = 0; kk < 36; kk++) {
        uint32_t koff = (uint32_t)kk*32u;   // kk*16 elems * 2B
        uint32_t ah0 = *(const uint32_t*)(smA_h + arow0 + koff);
        uint32_t ah1 = *(const uint32_t*)(smA_h + arow1 + koff);
        uint32_t ah2 = *(const uint32_t*)(smA_h + arow0 + koff + 16u);
        uint32_t ah3 = *(const uint32_t*)(smA_h + arow1 + koff + 16u);
        uint32_t al0 = *(const uint32_t*)(smA_l + arow0 + koff);
        uint32_t al1 = *(const uint32_t*)(smA_l + arow1 + koff);
        uint32_t al2 = *(const uint32_t*)(smA_l + arow0 + koff + 16u);
        uint32_t al3 = *(const uint32_t*)(smA_l + arow1 + koff + 16u);

        uint2 bh0 = fr0[(kk*2    )*32];
        uint2 bl0 = fr0[(kk*2 + 1)*32];
        uint2 bh1 = fr1[(kk*2    )*32];
        uint2 bl1 = fr1[(kk*2 + 1)*32];

        #define MMA(dd, a0_,a1_,a2_,a3_, b_) \
            asm volatile("mma.sync.aligned.m16n8k16.row.col.f32.bf16.bf16.f32 " \
                "{%0,%1,%2,%3}, {%4,%5,%6,%7}, {%8,%9}, {%0,%1,%2,%3};" \
                : "+f"(dd[0]), "+f"(dd[1]), "+f"(dd[2]), "+f"(dd[3]) \
                : "r"(a0_), "r"(a1_), "r"(a2_), "r"(a3_), "r"(b_.x), "r"(b_.y))

        MMA(d0, ah0,ah1,ah2,ah3, bh0);
        MMA(d0, ah0,ah1,ah2,ah3, bl0);
        MMA(d0, al0,al1,al2,al3, bh0);
        MMA(d1, ah0,ah1,ah2,ah3, bh1);
        MMA(d1, ah0,ah1,ah2,ah3, bl1);
        MMA(d1, al0,al1,al2,al3, bh1);
        #undef MMA
    }

    // ---- writeback: D fragment -> out[b][o][y][x] ----
    int px0 = x0 + mrow + g;            // rows g and g+8
    int obase = b*Oo*HW + y*Ww;
    #pragma unroll
    for (int j = 0; j < 2; j++) {
        float* dd = j ? d1 : d0;
        int on = ng*16 + j*8 + t4*2;    // cols t4*2, t4*2+1
        float bia0 = b_dcn[on];
        float bia1 = b_dcn[on+1];
        out[obase + on*HW     + px0    ] = dd[0] + bia0;
        out[obase + (on+1)*HW + px0    ] = dd[1] + bia1;
        out[obase + on*HW     + px0 + 8] = dd[2] + bia0;
        out[obase + (on+1)*HW + px0 + 8] = dd[3] + bia1;
    }
}

extern "C" void kernel_launch(void* const* d_in, const int* in_sizes, int n_in,
                              void* d_out, int out_size)
{
    const float* x      = (const float*)d_in[0];
    const float* w_off  = (const float*)d_in[1];
    const float* b_off  = (const float*)d_in[2];
    const float* w_mask = (const float*)d_in[3];
    const float* b_mask = (const float*)d_in[4];
    const float* w_dcn  = (const float*)d_in[5];
    const float* b_dcn  = (const float*)d_in[6];
    float* out = (float*)d_out;

    cudaFuncSetAttribute(offmask_kernel, cudaFuncAttributeMaxDynamicSharedMemorySize, SMEM_A);
    cudaFuncSetAttribute(dcn_kernel,     cudaFuncAttributeMaxDynamicSharedMemorySize, SMEM_B);

    prep_w<<<72, 256>>>(w_dcn);
    offmask_kernel<<<NBLK, 256, SMEM_A>>>(x, w_off, b_off, w_mask, b_mask);
    dcn_kernel<<<NBLK, 256, SMEM_B>>>(x, b_dcn, out);
}

// round 10
// speedup vs baseline: 3.3083x; 1.5897x over previous
#include <cuda_runtime.h>
#include <cuda_bf16.h>
#include <cstdint>
#include <math.h>

#define Hh 128
#define Ww 128
#define HW (Hh*Ww)
#define Cc 64
#define Oo 64
#define CK 576
#define PIX 32
#define NBLK (8*HW/PIX)   // 4096

// A planes (bf16): [32 px][584] per plane, hi then lo
#define ASTRIDE 584                      // elements; 1168 B row stride
#define APLANE  (PIX*ASTRIDE*2)          // 37376 B per plane
#define SMEM_B  (2*APLANE)               // 74752 B

extern __shared__ __align__(16) char _smem_raw[];

// scratch
__device__ float g_offmask[8*27*HW];                 // [B][27][H][W]
// DCN W fragments: [tile(8)][kk(36)][plane(2)][lane(32)] x uint2
__device__ __align__(16) uint2 g_wfrag[8*36*2*32];
// OffMask W fragments: [tile(4)][kk(36)][plane(2)][lane(32)] x uint2 (27 rows + zero pad)
__device__ __align__(16) uint2 g_wfrag_om[4*36*2*32];

// ---------------------------------------------------------------------------
// prep: pack weights into mma.sync B-fragment order, bf16 hi/lo planes.
// K ordered as k = tap*64 + c  (tap-major, channel inner).
// ---------------------------------------------------------------------------
__device__ __forceinline__ float wdcn_at(const float* w_dcn, int o, int k) {
    int c = k & 63, tap = k >> 6;
    return w_dcn[o*CK + c*9 + tap];
}
__device__ __forceinline__ float wom_at(const float* w_off, const float* w_mask, int o, int k) {
    int c = k & 63, tap = k >> 6;
    if (o < 18) return w_off[o*CK + c*9 + tap];
    if (o < 27) return w_mask[(o-18)*CK + c*9 + tap];
    return 0.f;
}
__device__ __forceinline__ uint2 pack4(float w0, float w1, float w2, float w3, int plane) {
    __nv_bfloat16 v0, v1, v2, v3;
    if (plane == 0) {
        v0 = __float2bfloat16(w0); v1 = __float2bfloat16(w1);
        v2 = __float2bfloat16(w2); v3 = __float2bfloat16(w3);
    } else {
        v0 = __float2bfloat16(w0 - __bfloat162float(__float2bfloat16(w0)));
        v1 = __float2bfloat16(w1 - __bfloat162float(__float2bfloat16(w1)));
        v2 = __float2bfloat16(w2 - __bfloat162float(__float2bfloat16(w2)));
        v3 = __float2bfloat16(w3 - __bfloat162float(__float2bfloat16(w3)));
    }
    __nv_bfloat162 p0; p0.x = v0; p0.y = v1;
    __nv_bfloat162 p1; p1.x = v2; p1.y = v3;
    uint2 r;
    r.x = *(uint32_t*)&p0;
    r.y = *(uint32_t*)&p1;
    return r;
}

#define NFRAG_DCN (8*36*2*32)   // 18432
#define NFRAG_OM  (4*36*2*32)   // 9216

__global__ void prep_w(const float* __restrict__ w_dcn,
                       const float* __restrict__ w_off,
                       const float* __restrict__ w_mask) {
    int i = blockIdx.x*256 + threadIdx.x;
    if (i < NFRAG_DCN) {
        int lane  = i & 31;
        int plane = (i >> 5) & 1;
        int kt    = i >> 6;
        int kk    = kt % 36;
        int tile  = kt / 36;
        int g  = lane >> 2;
        int t4 = lane & 3;
        int o  = tile*8 + g;
        int k0 = kk*16 + t4*2;
        g_wfrag[i] = pack4(wdcn_at(w_dcn, o, k0),   wdcn_at(w_dcn, o, k0+1),
                           wdcn_at(w_dcn, o, k0+8), wdcn_at(w_dcn, o, k0+9), plane);
    } else if (i < NFRAG_DCN + NFRAG_OM) {
        int j = i - NFRAG_DCN;
        int lane  = j & 31;
        int plane = (j >> 5) & 1;
        int kt    = j >> 6;
        int kk    = kt % 36;
        int tile  = kt / 36;
        int g  = lane >> 2;
        int t4 = lane & 3;
        int o  = tile*8 + g;
        int k0 = kk*16 + t4*2;
        g_wfrag_om[j] = pack4(wom_at(w_off, w_mask, o, k0),   wom_at(w_off, w_mask, o, k0+1),
                              wom_at(w_off, w_mask, o, k0+8), wom_at(w_off, w_mask, o, k0+9), plane);
    }
}

#define MMA(dd, a0_,a1_,a2_,a3_, b_) \
    asm volatile("mma.sync.aligned.m16n8k16.row.col.f32.bf16.bf16.f32 " \
        "{%0,%1,%2,%3}, {%4,%5,%6,%7}, {%8,%9}, {%0,%1,%2,%3};" \
        : "+f"(dd[0]), "+f"(dd[1]), "+f"(dd[2]), "+f"(dd[3]) \
        : "r"(a0_), "r"(a1_), "r"(a2_), "r"(a3_), "r"(b_.x), "r"(b_.y))

// ---------------------------------------------------------------------------
// Kernel A: offset/mask conv via mma.sync bf16 hi/lo (N=32: 27 real + pad).
// im2col straight into bf16 hi/lo smem planes (tap-major K).
// ---------------------------------------------------------------------------
__global__ __launch_bounds__(256) void offmask_kernel(
    const float* __restrict__ x,
    const float* __restrict__ b_off, const float* __restrict__ b_mask)
{
    char* smA_h = _smem_raw;            // [32][584] bf16 rows (1168 B)
    char* smA_l = _smem_raw + APLANE;

    int blk = blockIdx.x;
    int b   = blk >> 9;
    int rem = blk & 511;
    int y   = rem >> 2;
    int x0  = (rem & 3) << 5;
    int tid = threadIdx.x;

    const float* xb = x + b*Cc*HW;

    // im2col: 288 (p,tap) tasks; each loads 64 channels at one spatial point
    for (int task = tid; task < PIX*9; task += 256) {
        int p   = task & 31;
        int tap = task >> 5;
        int ki = tap / 3;
        int kj = tap - ki*3;
        int yy = y - 1 + ki;
        int xx = x0 + p - 1 + kj;
        uint32_t rowoff = (uint32_t)p*1168u + (uint32_t)tap*128u;
        if (yy >= 0 && yy < Hh && xx >= 0 && xx < Ww) {
            const float* base = xb + yy*Ww + xx;
            #pragma unroll 8
            for (int c = 0; c < Cc; c += 2) {
                float v0 = base[c*HW];
                float v1 = base[(c+1)*HW];
                __nv_bfloat16 h0 = __float2bfloat16(v0);
                __nv_bfloat16 h1 = __float2bfloat16(v1);
                __nv_bfloat16 l0 = __float2bfloat16(v0 - __bfloat162float(h0));
                __nv_bfloat16 l1 = __float2bfloat16(v1 - __bfloat162float(h1));
                __nv_bfloat162 hh; hh.x = h0; hh.y = h1;
                __nv_bfloat162 ll; ll.x = l0; ll.y = l1;
                *(uint32_t*)(smA_h + rowoff + c*2) = *(uint32_t*)&hh;
                *(uint32_t*)(smA_l + rowoff + c*2) = *(uint32_t*)&ll;
            }
        } else {
            #pragma unroll 8
            for (int c = 0; c < Cc; c += 2) {
                *(uint32_t*)(smA_h + rowoff + c*2) = 0u;
                *(uint32_t*)(smA_l + rowoff + c*2) = 0u;
            }
        }
    }
    __syncthreads();

    int wid  = tid >> 5;
    int lane = tid & 31;
    if (wid >= 4) return;               // 4 warps cover M=32 x N=32

    int mrow = (wid & 1) * 16;
    int ng   = wid >> 1;                // n16 group 0..1
    int g  = lane >> 2;
    int t4 = lane & 3;

    float d0[4] = {0.f,0.f,0.f,0.f};
    float d1[4] = {0.f,0.f,0.f,0.f};

    const uint2* fr0 = g_wfrag_om + ((ng*2    )*36)*2*32 + lane;
    const uint2* fr1 = g_wfrag_om + ((ng*2 + 1)*36)*2*32 + lane;

    uint32_t arow0 = (uint32_t)(mrow + g)*1168u + (uint32_t)t4*4u;
    uint32_t arow1 = arow0 + 8u*1168u;

    #pragma unroll 4
    for (int kk = 0; kk < 36; kk++) {
        uint32_t koff = (uint32_t)kk*32u;
        uint32_t ah0 = *(const uint32_t*)(smA_h + arow0 + koff);
        uint32_t ah1 = *(const uint32_t*)(smA_h + arow1 + koff);
        uint32_t ah2 = *(const uint32_t*)(smA_h + arow0 + koff + 16u);
        uint32_t ah3 = *(const uint32_t*)(smA_h + arow1 + koff + 16u);
        uint32_t al0 = *(const uint32_t*)(smA_l + arow0 + koff);
        uint32_t al1 = *(const uint32_t*)(smA_l + arow1 + koff);
        uint32_t al2 = *(const uint32_t*)(smA_l + arow0 + koff + 16u);
        uint32_t al3 = *(const uint32_t*)(smA_l + arow1 + koff + 16u);

        uint2 bh0 = fr0[(kk*2    )*32];
        uint2 bl0 = fr0[(kk*2 + 1)*32];
        uint2 bh1 = fr1[(kk*2    )*32];
        uint2 bl1 = fr1[(kk*2 + 1)*32];

        MMA(d0, ah0,ah1,ah2,ah3, bh0);
        MMA(d0, ah0,ah1,ah2,ah3, bl0);
        MMA(d0, al0,al1,al2,al3, bh0);
        MMA(d1, ah0,ah1,ah2,ah3, bh1);
        MMA(d1, ah0,ah1,ah2,ah3, bl1);
        MMA(d1, al0,al1,al2,al3, bh1);
    }

    // writeback -> g_offmask[b][o][y][x], sigmoid for o in [18,27)
    int px0 = x0 + mrow + g;
    int gbase = b*27*HW + y*Ww;
    #pragma unroll
    for (int j = 0; j < 2; j++) {
        float* dd = j ? d1 : d0;
        int on = ng*16 + j*8 + t4*2;
        #pragma unroll
        for (int e = 0; e < 2; e++) {
            int o = on + e;
            if (o >= 27) continue;
            float bias = (o < 18) ? b_off[o] : b_mask[o-18];
            float r0 = dd[e]   + bias;
            float r1 = dd[e+2] + bias;
            if (o >= 18) {
                r0 = 1.f/(1.f+expf(-r0));
                r1 = 1.f/(1.f+expf(-r1));
            }
            g_offmask[gbase + o*HW + px0    ] = r0;
            g_offmask[gbase + o*HW + px0 + 8] = r1;
        }
    }
}

// ---------------------------------------------------------------------------
// Kernel B (unchanged): sampling -> bf16 hi/lo planes -> mma.sync GEMM.
// ---------------------------------------------------------------------------
__global__ __launch_bounds__(256) void dcn_kernel(
    const float* __restrict__ x,
    const float* __restrict__ b_dcn,
    float* __restrict__ out)
{
    char* smA_h = _smem_raw;
    char* smA_l = _smem_raw + APLANE;

    int blk = blockIdx.x;
    int b   = blk >> 9;
    int rem = blk & 511;
    int y   = rem >> 2;
    int x0  = (rem & 3) << 5;
    int tid = threadIdx.x;

    const float* xb = x + b*Cc*HW;

    for (int task = tid; task < PIX*9; task += 256) {
        int p = task & 31;
        int k = task >> 5;
        int xx = x0 + p;

        const float* gb = g_offmask + b*27*HW + y*Ww + xx;
        float dy = gb[(2*k    )*HW];
        float dx = gb[(2*k + 1)*HW];
        float m  = gb[(18 + k )*HW];

        int ki = k / 3;
        int kj = k - ki*3;
        float py = (float)(y  - 1 + ki) + dy;
        float px = (float)(xx - 1 + kj) + dx;

        float fy = floorf(py), fx = floorf(px);
        float wy1 = py - fy, wx1 = px - fx;
        float wy0 = 1.f - wy1, wx0 = 1.f - wx1;

        float vy0 = (fy      >= 0.f && fy      <= 127.f) ? 1.f : 0.f;
        float vy1 = (fy+1.f  >= 0.f && fy+1.f  <= 127.f) ? 1.f : 0.f;
        float vx0 = (fx      >= 0.f && fx      <= 127.f) ? 1.f : 0.f;
        float vx1 = (fx+1.f  >= 0.f && fx+1.f  <= 127.f) ? 1.f : 0.f;

        int y0  = (int)fminf(fmaxf(fy,      0.f), 127.f);
        int y1  = (int)fminf(fmaxf(fy+1.f,  0.f), 127.f);
        int xq0 = (int)fminf(fmaxf(fx,      0.f), 127.f);
        int xq1 = (int)fminf(fmaxf(fx+1.f,  0.f), 127.f);

        int o00 = y0*Ww + xq0, o01 = y0*Ww + xq1;
        int o10 = y1*Ww + xq0, o11 = y1*Ww + xq1;
        float w00 = wy0*wx0*vy0*vx0*m;
        float w01 = wy0*wx1*vy0*vx1*m;
        float w10 = wy1*wx0*vy1*vx0*m;
        float w11 = wy1*wx1*vy1*vx1*m;

        uint32_t rowoff = (uint32_t)p*1168u + (uint32_t)k*128u;
        const float* xc = xb;
        #pragma unroll 8
        for (int c = 0; c < Cc; c += 2) {
            const float* c0 = xc;
            const float* c1 = xc + HW;
            float v0 = w00*c0[o00] + w01*c0[o01] + w10*c0[o10] + w11*c0[o11];
            float v1 = w00*c1[o00] + w01*c1[o01] + w10*c1[o10] + w11*c1[o11];
            __nv_bfloat16 h0 = __float2bfloat16(v0);
            __nv_bfloat16 h1 = __float2bfloat16(v1);
            __nv_bfloat16 l0 = __float2bfloat16(v0 - __bfloat162float(h0));
            __nv_bfloat16 l1 = __float2bfloat16(v1 - __bfloat162float(h1));
            __nv_bfloat162 hh; hh.x = h0; hh.y = h1;
            __nv_bfloat162 ll; ll.x = l0; ll.y = l1;
            *(uint32_t*)(smA_h + rowoff + c*2) = *(uint32_t*)&hh;
            *(uint32_t*)(smA_l + rowoff + c*2) = *(uint32_t*)&ll;
            xc += 2*HW;
        }
    }
    __syncthreads();

    int wid  = tid >> 5;
    int lane = tid & 31;
    int mrow = (wid & 1) * 16;
    int ng   = wid >> 1;
    int g  = lane >> 2;
    int t4 = lane & 3;

    float d0[4] = {0.f,0.f,0.f,0.f};
    float d1[4] = {0.f,0.f,0.f,0.f};

    const uint2* fr0 = g_wfrag + ((ng*2    )*36)*2*32 + lane;
    const uint2* fr1 = g_wfrag + ((ng*2 + 1)*36)*2*32 + lane;

    uint32_t arow0 = (uint32_t)(mrow + g)*1168u + (uint32_t)t4*4u;
    uint32_t arow1 = arow0 + 8u*1168u;

    #pragma unroll 4
    for (int kk = 0; kk < 36; kk++) {
        uint32_t koff = (uint32_t)kk*32u;
        uint32_t ah0 = *(const uint32_t*)(smA_h + arow0 + koff);
        uint32_t ah1 = *(const uint32_t*)(smA_h + arow1 + koff);
        uint32_t ah2 = *(const uint32_t*)(smA_h + arow0 + koff + 16u);
        uint32_t ah3 = *(const uint32_t*)(smA_h + arow1 + koff + 16u);
        uint32_t al0 = *(const uint32_t*)(smA_l + arow0 + koff);
        uint32_t al1 = *(const uint32_t*)(smA_l + arow1 + koff);
        uint32_t al2 = *(const uint32_t*)(smA_l + arow0 + koff + 16u);
        uint32_t al3 = *(const uint32_t*)(smA_l + arow1 + koff + 16u);

        uint2 bh0 = fr0[(kk*2    )*32];
        uint2 bl0 = fr0[(kk*2 + 1)*32];
        uint2 bh1 = fr1[(kk*2    )*32];
        uint2 bl1 = fr1[(kk*2 + 1)*32];

        MMA(d0, ah0,ah1,ah2,ah3, bh0);
        MMA(d0, ah0,ah1,ah2,ah3, bl0);
        MMA(d0, al0,al1,al2,al3, bh0);
        MMA(d1, ah0,ah1,ah2,ah3, bh1);
        MMA(d1, ah0,ah1,ah2,ah3, bl1);
        MMA(d1, al0,al1,al2,al3, bh1);
    }

    int px0 = x0 + mrow + g;
    int obase = b*Oo*HW + y*Ww;
    #pragma unroll
    for (int j = 0; j < 2; j++) {
        float* dd = j ? d1 : d0;
        int on = ng*16 + j*8 + t4*2;
        float bia0 = b_dcn[on];
        float bia1 = b_dcn[on+1];
        out[obase + on*HW     + px0    ] = dd[0] + bia0;
        out[obase + (on+1)*HW + px0    ] = dd[1] + bia1;
        out[obase + on*HW     + px0 + 8] = dd[2] + bia0;
        out[obase + (on+1)*HW + px0 + 8] = dd[3] + bia1;
    }
}

extern "C" void kernel_launch(void* const* d_in, const int* in_sizes, int n_in,
                              void* d_out, int out_size)
{
    const float* x      = (const float*)d_in[0];
    const float* w_off  = (const float*)d_in[1];
    const float* b_off  = (const float*)d_in[2];
    const float* w_mask = (const float*)d_in[3];
    const float* b_mask = (const float*)d_in[4];
    const float* w_dcn  = (const float*)d_in[5];
    const float* b_dcn  = (const float*)d_in[6];
    float* out = (float*)d_out;

    cudaFuncSetAttribute(offmask_kernel, cudaFuncAttributeMaxDynamicSharedMemorySize, SMEM_B);
    cudaFuncSetAttribute(dcn_kernel,     cudaFuncAttributeMaxDynamicSharedMemorySize, SMEM_B);

    prep_w<<<108, 256>>>(w_dcn, w_off, w_mask);
    offmask_kernel<<<NBLK, 256, SMEM_B>>>(x, b_off, b_mask);
    dcn_kernel<<<NBLK, 256, SMEM_B>>>(x, b_dcn, out);
}